// round 7
// baseline (speedup 1.0000x reference)
#include <cuda_runtime.h>
#include <cstdint>

// LSTMTagger: 262144 sequential steps, H=128 (512 gate rows), I=2.
// R6: 4-CTA cluster, 128 thr/CTA, all 128 W_hh cols per gate row in regs
// (permuted so own-CTA slice is first -> static reg indexing).
// Exchange: shfl-pack h slice into 8 lanes x float4 st.shared::cluster
// (32 barrier arrivals/step, was 128), overlapped with own-slice partial
// gemv; h triple-buffered. Full fp32 numerics.

#define L_SEQ     262144
#define H_DIM     128
#define SLICE     32
#define CLUSTER_N 4
#define NTHREADS  128
#define CHUNK     1024

__device__ __forceinline__ float sigmoid_f(float x) {
    return __fdividef(1.0f, 1.0f + __expf(-x));
}
__device__ __forceinline__ float tanh_f(float x) {
    return 1.0f - __fdividef(2.0f, 1.0f + __expf(2.0f * x));
}

__device__ __forceinline__ uint32_t smem_u32(const void* p) {
    uint32_t a;
    asm("{ .reg .u64 t; cvta.to.shared.u64 t, %1; cvt.u32.u64 %0, t; }"
        : "=r"(a) : "l"(p));
    return a;
}
__device__ __forceinline__ uint32_t cluster_rank() {
    uint32_t r; asm("mov.u32 %0, %%cluster_ctarank;" : "=r"(r)); return r;
}
__device__ __forceinline__ uint32_t mapa_u32(uint32_t addr, uint32_t rank) {
    uint32_t r;
    asm("mapa.shared::cluster.u32 %0, %1, %2;" : "=r"(r) : "r"(addr), "r"(rank));
    return r;
}
__device__ __forceinline__ void sts_cluster_v4(uint32_t raddr, float a, float b,
                                               float c, float d) {
    asm volatile("st.shared::cluster.v4.f32 [%0], {%1,%2,%3,%4};"
                 :: "r"(raddr), "f"(a), "f"(b), "f"(c), "f"(d) : "memory");
}
__device__ __forceinline__ void mbar_arrive_cluster(uint32_t raddr) {
    asm volatile("mbarrier.arrive.shared::cluster.b64 _, [%0];"
                 :: "r"(raddr) : "memory");
}
__device__ __forceinline__ void mbar_init(uint32_t addr, uint32_t count) {
    asm volatile("mbarrier.init.shared.b64 [%0], %1;"
                 :: "r"(addr), "r"(count) : "memory");
}
__device__ __forceinline__ void mbar_wait_parity_acq_cluster(uint32_t addr,
                                                             uint32_t parity) {
    uint32_t done;
    asm volatile(
        "{\n\t.reg .pred p;\n\t"
        "mbarrier.try_wait.parity.acquire.cluster.shared::cta.b64 p, [%1], %2;\n\t"
        "selp.b32 %0, 1, 0, p;\n\t}"
        : "=r"(done) : "r"(addr), "r"(parity) : "memory");
    if (!done) {
        asm volatile(
            "{\n\t.reg .pred P1;\n\t"
            "WL_%=:\n\t"
            "mbarrier.try_wait.parity.acquire.cluster.shared::cta.b64 P1, [%0], %1, 0x989680;\n\t"
            "@P1 bra.uni WD_%=;\n\t"
            "bra.uni WL_%=;\n\t"
            "WD_%=:\n\t}"
            :: "r"(addr), "r"(parity) : "memory");
    }
}
#define CLUSTER_SYNC_() do { \
    asm volatile("barrier.cluster.arrive.aligned;" ::: "memory"); \
    asm volatile("barrier.cluster.wait.aligned;" ::: "memory"); \
} while (0)

__global__ void __launch_bounds__(NTHREADS, 1) __cluster_dims__(CLUSTER_N, 1, 1)
lstm_cluster_kernel(const float* __restrict__ sentence,
                    const float* __restrict__ W_ih,
                    const float* __restrict__ W_hh,
                    const float* __restrict__ b_ih,
                    const float* __restrict__ b_hh,
                    const float* __restrict__ W_out,
                    const float* __restrict__ b_out,
                    float* __restrict__ out)
{
    __shared__ alignas(8)  unsigned long long mbar;
    __shared__ alignas(16) float hbuf[3][H_DIM];   // triple buffer
    __shared__ alignas(16) float gact[NTHREADS];
    __shared__ alignas(16) float xbuf[CHUNK * 2];

    const int r    = threadIdx.x;     // 0..127
    const int lane = r & 31;
    const int gate = r >> 5;          // 0=i 1=f 2=g(tanh) 3=o (warp-uniform)
    const uint32_t rank = cluster_rank();

    const int gr = gate * H_DIM + (int)rank * SLICE + lane;  // global gate row

    const float wih0 = W_ih[2 * gr + 0];
    const float wih1 = W_ih[2 * gr + 1];
    const float br   = b_ih[gr] + b_hh[gr];

    // W_hh row in registers, PERMUTED so own-slice cols come first:
    // W[m] corresponds to h column ((32*rank + m) & 127). All reg indices
    // in the hot loop are compile-time constants.
    float W[H_DIM];
#pragma unroll
    for (int m = 0; m < H_DIM; ++m)
        W[m] = W_hh[gr * H_DIM + (((int)rank * SLICE + m) & (H_DIM - 1))];

    // init
    hbuf[0][r] = 0.0f; if (r < H_DIM) { hbuf[1][r] = 0.0f; hbuf[2][r] = 0.0f; }
    const uint32_t bar_addr = smem_u32(&mbar);
    const uint32_t hb_addr  = smem_u32(&hbuf[0][0]);
    if (r == 0) mbar_init(bar_addr, 8 * CLUSTER_N);   // 32 arrivals per phase
    __syncthreads();
    CLUSTER_SYNC_();

    // remote peer addresses (exclude self)
    uint32_t rpeer_h[CLUSTER_N - 1], rpeer_bar[CLUSTER_N - 1];
#pragma unroll
    for (int i = 0; i < CLUSTER_N - 1; ++i) {
        const uint32_t p = (rank + 1u + (uint32_t)i) & (CLUSTER_N - 1);
        rpeer_h[i]   = mapa_u32(hb_addr, p);
        rpeer_bar[i] = mapa_u32(bar_addr, p);
    }
    // packed-store byte offset within a buffer (lanes 0..7 use it)
    const uint32_t pk_off = rank * (SLICE * 4u) + (uint32_t)lane * 16u;

    int rb = 0, wb = 1, xb = 2;       // rotating buffer indices
    float c_reg = 0.0f;               // gate-0 lanes: c[32*rank + lane]
    float part  = 0.0f;               // own-slice partial dot (h(0)=0)

    for (int t0 = 0; t0 < L_SEQ; t0 += CHUNK) {
        // refill x chunk: 2048 floats = 512 float4
        {
            const float4* src = (const float4*)(sentence + 2 * t0);
            float4* dst = (float4*)xbuf;
#pragma unroll
            for (int j = 0; j < 4; ++j) dst[r + j * NTHREADS] = src[r + j * NTHREADS];
        }
        __syncthreads();

#pragma unroll 1
        for (int ti = 0; ti < CHUNK; ++ti) {
            const int t = t0 + ti;
            // (a) finish g(t): x-term + own partial + 3 remote slices
            const float x0 = xbuf[2 * ti + 0];
            const float x1 = xbuf[2 * ti + 1];
            float acc0 = fmaf(wih0, x0, br) + part;
            float acc1 = wih1 * x1;
            float acc2 = 0.0f, acc3 = 0.0f;
            {
                const float* hr = &hbuf[rb][0];
#pragma unroll
                for (int i = 1; i < CLUSTER_N; ++i) {
                    const uint32_t s = (rank + (uint32_t)i) & (CLUSTER_N - 1);
                    const float4* h4 = (const float4*)(hr + s * SLICE);
#pragma unroll
                    for (int q = 0; q < SLICE / 4; ++q) {
                        const float4 hv = h4[q];
                        acc0 = fmaf(W[SLICE * i + 4 * q + 0], hv.x, acc0);
                        acc1 = fmaf(W[SLICE * i + 4 * q + 1], hv.y, acc1);
                        acc2 = fmaf(W[SLICE * i + 4 * q + 2], hv.z, acc2);
                        acc3 = fmaf(W[SLICE * i + 4 * q + 3], hv.w, acc3);
                    }
                }
            }
            const float g = (acc0 + acc2) + (acc1 + acc3);

            // (b) activation, publish to gact
            gact[r] = (gate == 2) ? tanh_f(g) : sigmoid_f(g);
            __syncthreads();                                   // S1

            // (c) producer warp: c/h update, local store, packed remote push
            if (gate == 0) {
                const float iv = gact[lane];
                const float fv = gact[32 + lane];
                const float gv = gact[64 + lane];
                const float ov = gact[96 + lane];
                c_reg = fmaf(fv, c_reg, iv * gv);
                const float h = ov * tanh_f(c_reg);

                hbuf[wb][rank * SLICE + lane] = h;             // local slice

                const float v0 = __shfl_sync(0xffffffffu, h, 4 * lane + 0);
                const float v1 = __shfl_sync(0xffffffffu, h, 4 * lane + 1);
                const float v2 = __shfl_sync(0xffffffffu, h, 4 * lane + 2);
                const float v3 = __shfl_sync(0xffffffffu, h, 4 * lane + 3);
                if (lane < 8) {
                    const uint32_t off = (uint32_t)wb * (H_DIM * 4u) + pk_off;
#pragma unroll
                    for (int i = 0; i < CLUSTER_N - 1; ++i)
                        sts_cluster_v4(rpeer_h[i] + off, v0, v1, v2, v3);
                    mbar_arrive_cluster(bar_addr);             // own count
#pragma unroll
                    for (int i = 0; i < CLUSTER_N - 1; ++i)
                        mbar_arrive_cluster(rpeer_bar[i]);
                }
            }
            __syncthreads();                                   // S2

            // (d) overlap: own-slice partial of g(t+1) while DSMEM in flight
            {
                const float4* h4 = (const float4*)(&hbuf[wb][0] + rank * SLICE);
                float p0 = 0.0f, p1 = 0.0f, p2 = 0.0f, p3 = 0.0f;
#pragma unroll
                for (int q = 0; q < SLICE / 4; ++q) {
                    const float4 hv = h4[q];
                    p0 = fmaf(W[4 * q + 0], hv.x, p0);
                    p1 = fmaf(W[4 * q + 1], hv.y, p1);
                    p2 = fmaf(W[4 * q + 2], hv.z, p2);
                    p3 = fmaf(W[4 * q + 3], hv.w, p3);
                }
                part = (p0 + p2) + (p1 + p3);
            }

            // (e) wait for remote slices of h(t+1)
            mbar_wait_parity_acq_cluster(bar_addr, (uint32_t)(t & 1));

            // (f) rotate buffers
            const int tmp = rb; rb = wb; wb = xb; xb = tmp;
        }
    }

    // Outputs: out[0]=sigmoid(h.W_out+b), out[1..128]=h_n, out[129..256]=c_n
    if (gate == 0)
        out[1 + H_DIM + (int)rank * SLICE + lane] = c_reg;
    if (rank == 0) {
        out[1 + r] = hbuf[rb][r];
        if (r < 32) {
            float s = 0.0f;
#pragma unroll
            for (int m = 0; m < 4; ++m)
                s = fmaf(hbuf[rb][4 * r + m], W_out[4 * r + m], s);
#pragma unroll
            for (int off = 16; off > 0; off >>= 1)
                s += __shfl_xor_sync(0xffffffffu, s, off);
            if (r == 0) out[0] = sigmoid_f(s + b_out[0]);
        }
    }
    CLUSTER_SYNC_();
}

extern "C" void kernel_launch(void* const* d_in, const int* in_sizes, int n_in,
                              void* d_out, int out_size)
{
    const float* sentence = (const float*)d_in[0];
    const float* W_ih     = (const float*)d_in[1];
    const float* W_hh     = (const float*)d_in[2];
    const float* b_ih     = (const float*)d_in[3];
    const float* b_hh     = (const float*)d_in[4];
    const float* W_out    = (const float*)d_in[5];
    const float* b_out    = (const float*)d_in[6];
    float* out            = (float*)d_out;

    lstm_cluster_kernel<<<CLUSTER_N, NTHREADS>>>(
        sentence, W_ih, W_hh, b_ih, b_hh, W_out, b_out, out);
}